// round 15
// baseline (speedup 1.0000x reference)
#include <cuda_runtime.h>
#include <cstdint>

// GlobalAttentionModule_7438883356930
//
// Identity: softmax row-sums are 1 and v is constant along the softmaxed axis,
// so out = relu(GroupNorm_32(Wv @ feat + bv)). (Verified: rel_err ~1e-7.)
//
// R14: NO cluster. 64 blocks (one per (batch,group), full group in-block so
// GN stats need only bar.sync), 512 threads, k split 4 ways. FFMA2 packed
// mainloop (R12-validated) keeps per-SMSP FMA issue at 2048 cyc despite the
// doubled per-warp work; 32 feat LDG.128 double-buffered in 4 chunks of 8.

#define C_DIM    128
#define N_DIM    512
#define B_DIM    2
#define GROUPS   32
#define CPG      4
#define NF4      (N_DIM / 4)           // 128 float4 n-positions
#define KSPLIT   4
#define KPART    (C_DIM / KSPLIT)      // 32
#define NCHNK    4                     // load/FMA chunks per thread
#define CHNK     (KPART / NCHNK)       // 8 k per chunk
#define THREADS  (KSPLIT * NF4)        // 512
#define EPS      1e-5f

#define FMA2(acc, a, b) \
    asm("fma.rn.f32x2 %0, %1, %2, %0;" : "+l"(acc) : "l"(a), "l"(b))
#define ADD2(acc, a) \
    asm("add.rn.f32x2 %0, %0, %1;" : "+l"(acc) : "l"(a))
#define DUP2(d, s) \
    asm("mov.b64 %0, {%1, %1};" : "=l"(d) : "f"(s))
#define UNPK2(lo, hi, s) \
    asm("mov.b64 {%0, %1}, %2;" : "=f"(lo), "=f"(hi) : "l"(s))

__global__ __launch_bounds__(THREADS)
void fused_nocluster(const float* __restrict__ feat,   // [B, C, N]
                     const float* __restrict__ Wv,     // [C, C]
                     const float* __restrict__ bv,     // [C]
                     const float* __restrict__ gamma,  // [C]
                     const float* __restrict__ beta,   // [C]
                     float* __restrict__ out)          // [B, C, N]
{
    const int b = blockIdx.x / GROUPS;
    const int g = blockIdx.x % GROUPS;
    const int t = threadIdx.x;

    __shared__ float4 wT[C_DIM];                    // 2 KB: wT[k] = {w_c0..w_c3}[k]
    __shared__ float4 scomb[KSPLIT - 1][CPG][NF4];  // 24 KB: slices 1..3 partials
    __shared__ float  red_s[4], red_ss[4];
    __shared__ float  s_mean, s_rstd;

    const int q = t >> 7;          // k-slice 0..3
    const int j = t & 127;         // float4 n index 0..127

    const float* fb = feat + (size_t)b * C_DIM * N_DIM
                    + (size_t)(q * KPART) * N_DIM + 4 * j;

    // ---- chunk 0 loads front-batched (overlap weight staging) ----
    ulonglong2 xa[CHNK], xb[CHNK];
    #pragma unroll
    for (int i = 0; i < CHNK; i++)
        xa[i] = *reinterpret_cast<const ulonglong2*>(fb + (size_t)i * N_DIM);

    // ---- stage weights transposed ----
    {
        const int k  = t & 127;
        const int cc = t >> 7;     // 0..3
        reinterpret_cast<float*>(&wT[k])[cc] = Wv[(size_t)(g * CPG + cc) * C_DIM + k];
    }
    __syncthreads();

    // ---- FFMA2 mainloop: 4ch x 4n, 32 k, double-buffered in 4 chunks ----
    unsigned long long A0l = 0, A0h = 0, A1l = 0, A1h = 0;
    unsigned long long A2l = 0, A2h = 0, A3l = 0, A3h = 0;
    #pragma unroll
    for (int ch = 0; ch < NCHNK; ch++) {
        ulonglong2* cur = (ch & 1) ? xb : xa;
        ulonglong2* nxt = (ch & 1) ? xa : xb;
        if (ch < NCHNK - 1) {
            #pragma unroll
            for (int i = 0; i < CHNK; i++)
                nxt[i] = *reinterpret_cast<const ulonglong2*>(
                    fb + (size_t)((ch + 1) * CHNK + i) * N_DIM);
        }
        #pragma unroll
        for (int kk = 0; kk < CHNK; kk++) {
            const float4 wv = wT[q * KPART + ch * CHNK + kk];
            unsigned long long w0, w1, w2, w3;
            DUP2(w0, wv.x); DUP2(w1, wv.y); DUP2(w2, wv.z); DUP2(w3, wv.w);
            const unsigned long long xl = cur[kk].x, xh = cur[kk].y;
            FMA2(A0l, w0, xl); FMA2(A0h, w0, xh);
            FMA2(A1l, w1, xl); FMA2(A1h, w1, xh);
            FMA2(A2l, w2, xl); FMA2(A2h, w2, xh);
            FMA2(A3l, w3, xl); FMA2(A3h, w3, xh);
        }
    }

    // ---- slices 1..3 publish; slice 0 folds ----
    if (q > 0) {
        *reinterpret_cast<ulonglong2*>(&scomb[q - 1][0][j]) = make_ulonglong2(A0l, A0h);
        *reinterpret_cast<ulonglong2*>(&scomb[q - 1][1][j]) = make_ulonglong2(A1l, A1h);
        *reinterpret_cast<ulonglong2*>(&scomb[q - 1][2][j]) = make_ulonglong2(A2l, A2h);
        *reinterpret_cast<ulonglong2*>(&scomb[q - 1][3][j]) = make_ulonglong2(A3l, A3h);
    }
    __syncthreads();

    float v[CPG][4];               // unpacked final values (t<128 only)
    float ga[CPG], be[CPG];

    if (q == 0) {
        #pragma unroll
        for (int r = 0; r < KSPLIT - 1; r++) {
            ulonglong2 p;
            p = *reinterpret_cast<const ulonglong2*>(&scomb[r][0][j]);
            ADD2(A0l, p.x); ADD2(A0h, p.y);
            p = *reinterpret_cast<const ulonglong2*>(&scomb[r][1][j]);
            ADD2(A1l, p.x); ADD2(A1h, p.y);
            p = *reinterpret_cast<const ulonglong2*>(&scomb[r][2][j]);
            ADD2(A2l, p.x); ADD2(A2h, p.y);
            p = *reinterpret_cast<const ulonglong2*>(&scomb[r][3][j]);
            ADD2(A3l, p.x); ADD2(A3h, p.y);
        }
        const int c0 = g * CPG;
        unsigned long long bb;
        DUP2(bb, bv[c0 + 0]); ADD2(A0l, bb); ADD2(A0h, bb);
        DUP2(bb, bv[c0 + 1]); ADD2(A1l, bb); ADD2(A1h, bb);
        DUP2(bb, bv[c0 + 2]); ADD2(A2l, bb); ADD2(A2h, bb);
        DUP2(bb, bv[c0 + 3]); ADD2(A3l, bb); ADD2(A3h, bb);

        UNPK2(v[0][0], v[0][1], A0l); UNPK2(v[0][2], v[0][3], A0h);
        UNPK2(v[1][0], v[1][1], A1l); UNPK2(v[1][2], v[1][3], A1h);
        UNPK2(v[2][0], v[2][1], A2l); UNPK2(v[2][2], v[2][3], A2h);
        UNPK2(v[3][0], v[3][1], A3l); UNPK2(v[3][2], v[3][3], A3h);

        #pragma unroll
        for (int cc = 0; cc < CPG; cc++) {          // prefetch affine params
            ga[cc] = gamma[c0 + cc];
            be[cc] = beta[c0 + cc];
        }

        // stats over this thread's 16 values, then 4-warp reduce
        float s = 0.f, ss = 0.f;
        #pragma unroll
        for (int cc = 0; cc < CPG; cc++)
            #pragma unroll
            for (int i = 0; i < 4; i++) {
                const float x = v[cc][i];
                s += x; ss += x * x;
            }
        #pragma unroll
        for (int o = 16; o > 0; o >>= 1) {
            s  += __shfl_xor_sync(0xffffffffu, s,  o);
            ss += __shfl_xor_sync(0xffffffffu, ss, o);
        }
        const int warp = t >> 5, lane = t & 31;     // warps 0..3
        if (lane == 0) { red_s[warp] = s; red_ss[warp] = ss; }
    }
    __syncthreads();

    if (t == 0) {
        const float ts  = red_s[0] + red_s[1] + red_s[2] + red_s[3];
        const float tss = red_ss[0] + red_ss[1] + red_ss[2] + red_ss[3];
        const float inv = 1.0f / (float)(CPG * N_DIM);
        const float m   = ts * inv;
        const float var = tss * inv - m * m;
        s_mean = m;
        s_rstd = rsqrtf(var + EPS);
    }
    __syncthreads();

    // ---- normalize + affine + relu + store (t<128, 4 STG.128 each) ----
    if (q == 0) {
        const float m = s_mean, r = s_rstd;
        const int  c0 = g * CPG;
        float* ob = out + ((size_t)b * C_DIM + c0) * N_DIM + 4 * j;
        #pragma unroll
        for (int cc = 0; cc < CPG; cc++) {
            const float gr = ga[cc] * r;
            float4 o4;
            o4.x = fmaxf(fmaf(v[cc][0] - m, gr, be[cc]), 0.f);
            o4.y = fmaxf(fmaf(v[cc][1] - m, gr, be[cc]), 0.f);
            o4.z = fmaxf(fmaf(v[cc][2] - m, gr, be[cc]), 0.f);
            o4.w = fmaxf(fmaf(v[cc][3] - m, gr, be[cc]), 0.f);
            *reinterpret_cast<float4*>(ob + (size_t)cc * N_DIM) = o4;
        }
    }
}

extern "C" void kernel_launch(void* const* d_in, const int* in_sizes, int n_in,
                              void* d_out, int out_size)
{
    // 0 feat, 1 Wk, 2 bk, 3 Wq, 4 bq, 5 Wv, 6 bv, 7 gn_v_g, 8 gn_v_b, ...
    const float* feat = (const float*)d_in[0];
    const float* Wv   = (const float*)d_in[5];
    const float* bv   = (const float*)d_in[6];
    const float* gn_g = (const float*)d_in[7];
    const float* gn_b = (const float*)d_in[8];
    float* out = (float*)d_out;

    fused_nocluster<<<B_DIM * GROUPS, THREADS>>>(feat, Wv, bv, gn_g, gn_b, out);
}